// round 12
// baseline (speedup 1.0000x reference)
#include <cuda_runtime.h>
#include <cuda_bf16.h>

// ---------------- problem constants ----------------
#define EPS_BN 1e-5f
constexpr int Bn   = 64;          // batch
constexpr int Cin  = 64;
constexpr int Cout = 128;
constexpr int Tn   = 300;
constexpr int Vn   = 25;
constexpr int SPB  = Tn * Vn;     // 7500 sites per (b, channel)
constexpr float NTOT = 480000.0f; // B*T*V

constexpr int STILE  = 128;
constexpr int NSTILE = (SPB + STILE - 1) / STILE;  // 59
constexpr int NBLK2  = Bn * NSTILE;                // 3776

// ---------------- device workspaces (no allocs allowed) ----------------
// z is staged in d_out; k_gemm fully rewrites it on every launch before
// k_apply reads it, so graph replays stay deterministic.
__device__ __align__(16) float g_xg[Bn * Cin * SPB];    // 122.88 MB
__device__ __align__(16) float g_Wt[Cin * Cout];        // W transposed: [c][o]
__device__ float g_psum[Cout * NBLK2];                  // [o][blk]
__device__ float g_psq [Cout * NBLK2];
__device__ float g_coef[2 * Cout];                      // alpha, then bias'

// packed f32x2 FMA (SASS FFMA2) — only reachable via explicit PTX
#define FMA2(a, x, y) asm("fma.rn.f32x2 %0, %1, %2, %0;" : "+l"(a) : "l"(x), "l"(y))

union UF2 { unsigned long long u; float2 f; };

// ---------------- K1: xg = x @ adj, one 25-float row per thread -----------------
__global__ void k_xg(const float* __restrict__ x, const float* __restrict__ adj) {
    __shared__ float sx[256 * 25];    // 25.6 KB
    __shared__ float sadj[625];
    const int tid = threadIdx.x;
    const long long base = (long long)blockIdx.x * (256 * 25);

    #pragma unroll 4
    for (int i = tid; i < 256 * 25; i += 256) sx[i] = x[base + i];
    for (int i = tid; i < 625; i += 256) sadj[i] = adj[i];
    __syncthreads();

    float xr[25];
    #pragma unroll
    for (int v = 0; v < 25; v++) xr[v] = sx[tid * 25 + v];

    #pragma unroll 5
    for (int w = 0; w < 25; w++) {
        float a0 = 0.f;
        #pragma unroll
        for (int v = 0; v < 25; v++)
            a0 = fmaf(xr[v], sadj[v * 25 + w], a0);   // adj read is warp-broadcast
        sx[tid * 25 + w] = a0;
    }
    __syncthreads();

    #pragma unroll 4
    for (int i = tid; i < 256 * 25; i += 256) g_xg[base + i] = sx[i];
}

// ---------------- K1b: transpose W (Cout,Cin) -> [c][o] -------------------------
// Idempotent (pure function of W). Launched twice: the second launch is a
// deliberate pad so ncu's fixed profile window (-s 5 -c 1, empirically
// sequence index 3) lands on k_gemm instead of k_stats.
__global__ void k_wt(const float* __restrict__ W) {
    int i = blockIdx.x * 256 + threadIdx.x;      // 8192 items
    if (i < Cout * Cin) {
        int o = i >> 6, c = i & 63;              // W row-major (o, c)
        g_Wt[c * Cout + o] = W[i];
    }
}

// ---------------- K2: z[b,o,s] = sum_c W[o,c]*xg[b,c,s] + BN partials -----------
// o-pairs packed from W (contiguous in [c][o] layout); x duplicated in regs.
// Per k-step/thread: 4x LDS.128, 32 FFMA2 -> FMA2-pipe bound.
__global__ void __launch_bounds__(256, 2) k_gemm(float* __restrict__ zout) {
    extern __shared__ float sm[];
    float* sW = sm;                // 64 * 128 floats (32 KB), [k][o]
    float* sX = sm + 8192;         // 64 * 128 floats (32 KB), [k][s]

    const int tid = threadIdx.x;
    const int tx = tid & 15, ty = tid >> 4;      // 16 x 16 thread grid
    const int b  = blockIdx.y;
    const int s0 = blockIdx.x * STILE;
    int valid = SPB - s0; if (valid > STILE) valid = STILE;

    #pragma unroll 4
    for (int i = tid; i < 8192; i += 256) sW[i] = g_Wt[i];   // already [c][o]
    #pragma unroll 4
    for (int i = tid; i < 8192; i += 256) {
        int c = i >> 7, s = i & 127;
        sX[i] = (s < valid) ? g_xg[((long long)(b * Cin + c)) * SPB + s0 + s] : 0.f;
    }
    __syncthreads();

    // acc[p][j]: p = o-pair (o0+2p, o0+2p+1), j = site index (tx*8 + j)
    unsigned long long acc[4][8];
    #pragma unroll
    for (int p = 0; p < 4; p++)
        #pragma unroll
        for (int j = 0; j < 8; j++) acc[p][j] = 0ULL;

    const float* wp = sW + ty * 8;     // 8 o values = 4 natural pairs
    const float* xp = sX + tx * 8;     // 8 sites

    #pragma unroll 2
    for (int k = 0; k < 64; k++) {
        ulonglong2 wa = *(const ulonglong2*)(wp);       // pairs (0,1),(2,3)
        ulonglong2 wb = *(const ulonglong2*)(wp + 4);   // pairs (4,5),(6,7)
        float4 xa = *(const float4*)(xp);
        float4 xb = *(const float4*)(xp + 4);
        float xs[8] = {xa.x, xa.y, xa.z, xa.w, xb.x, xb.y, xb.z, xb.w};
        #pragma unroll
        for (int j = 0; j < 8; j++) {
            UF2 d; d.f.x = xs[j]; d.f.y = xs[j];        // dup-pack: 2 MOVs (alu pipe)
            FMA2(acc[0][j], wa.x, d.u);
            FMA2(acc[1][j], wa.y, d.u);
            FMA2(acc[2][j], wb.x, d.u);
            FMA2(acc[3][j], wb.y, d.u);
        }
        wp += 128; xp += 128;
    }

    // ---- epilogue: write z + deterministic per-o partial sums ----
    const int o0 = ty * 8;
    const int blk = blockIdx.y * NSTILE + blockIdx.x;
    const long long zbase = ((long long)b * Cout) * SPB + s0 + tx * 8;

    #pragma unroll
    for (int i = 0; i < 8; i++) {
        const int p = i >> 1, h = i & 1;
        float vals[8];
        #pragma unroll
        for (int j = 0; j < 8; j++) {
            UF2 cv; cv.u = acc[p][j];
            vals[j] = h ? cv.f.y : cv.f.x;
        }
        float s = 0.f, q = 0.f;
        #pragma unroll
        for (int j = 0; j < 8; j++) { s += vals[j]; q = fmaf(vals[j], vals[j], q); }
        // zero-padded tail sites contribute exact zeros to s and q.
        #pragma unroll
        for (int d = 8; d > 0; d >>= 1) {       // deterministic width-16 tree
            s += __shfl_down_sync(0xffffffffu, s, d, 16);
            q += __shfl_down_sync(0xffffffffu, q, d, 16);
        }
        if (tx == 0) {
            g_psum[(o0 + i) * NBLK2 + blk] = s;
            g_psq [(o0 + i) * NBLK2 + blk] = q;
        }
        long long zp = zbase + (long long)(o0 + i) * SPB;
        if (tx * 8 + 8 <= valid) {
            float4* ptr = (float4*)(zout + zp);
            ptr[0] = make_float4(vals[0], vals[1], vals[2], vals[3]);
            ptr[1] = make_float4(vals[4], vals[5], vals[6], vals[7]);
        } else {
            #pragma unroll
            for (int j = 0; j < 8; j++)
                if (tx * 8 + j < valid) zout[zp + j] = vals[j];
        }
    }
}

// ---------------- K3: reduce partials -> per-channel affine coefficients --------
__global__ void k_stats(const float* __restrict__ gamma, const float* __restrict__ beta) {
    const int o   = blockIdx.x;      // 0..127
    const int tid = threadIdx.x;     // 256 threads
    const float* ps = g_psum + o * NBLK2;
    const float* pq = g_psq  + o * NBLK2;

    float s = 0.f, q = 0.f;
    for (int bk = tid; bk < NBLK2; bk += 256) {  // coalesced
        s += ps[bk];
        q += pq[bk];
    }
    __shared__ float ss[256], sq[256];
    ss[tid] = s; sq[tid] = q;
    __syncthreads();
    #pragma unroll
    for (int d = 128; d > 0; d >>= 1) {
        if (tid < d) { ss[tid] += ss[tid + d]; sq[tid] += sq[tid + d]; }
        __syncthreads();
    }
    if (tid == 0) {
        float mean  = ss[0] / NTOT;
        float var   = sq[0] / NTOT - mean * mean;  // biased var; conv bias cancels
        float alpha = gamma[o] * rsqrtf(var + EPS_BN);
        g_coef[o]        = alpha;
        g_coef[Cout + o] = beta[o] - alpha * mean;
    }
}

// ---------------- K4: out = relu(alpha*z + bias')  in-place on d_out ------------
__global__ void k_apply(float* __restrict__ out, int n4) {
    int i = blockIdx.x * blockDim.x + threadIdx.x;
    if (i >= n4) return;
    int o = (i / (SPB / 4)) & (Cout - 1);        // (b*128+o) mod 128
    float al = g_coef[o], bb = g_coef[Cout + o];
    const float4 z = ((const float4*)out)[i];
    float4 r;
    r.x = fmaxf(fmaf(al, z.x, bb), 0.f);
    r.y = fmaxf(fmaf(al, z.y, bb), 0.f);
    r.z = fmaxf(fmaf(al, z.z, bb), 0.f);
    r.w = fmaxf(fmaf(al, z.w, bb), 0.f);
    ((float4*)out)[i] = r;
}

// ---------------- launch ----------------
extern "C" void kernel_launch(void* const* d_in, const int* in_sizes, int n_in,
                              void* d_out, int out_size) {
    const float* x     = (const float*)d_in[0];   // (64,64,300,25)
    const float* adj   = (const float*)d_in[1];   // (25,25)
    const float* W     = (const float*)d_in[2];   // (128,64)
    // d_in[3] = conv bias — cancels exactly under BatchNorm, unused
    const float* gamma = (const float*)d_in[4];   // (128,)
    const float* beta  = (const float*)d_in[5];   // (128,)
    float* out = (float*)d_out;

    const int SMEM2 = (8192 + 8192) * (int)sizeof(float);       // 64 KB
    cudaFuncSetAttribute(k_gemm, cudaFuncAttributeMaxDynamicSharedMemorySize, SMEM2);

    k_xg<<<4800, 256>>>(x, adj);                  // launch index 0
    k_wt<<<32, 256>>>(W);                         // index 1
    k_wt<<<32, 256>>>(W);                         // index 2 — idempotent pad so the
                                                  // profiler window (index 3) = k_gemm
    k_gemm<<<dim3(NSTILE, Bn), 256, SMEM2>>>(out);// index 3  <-- ncu target
    k_stats<<<Cout, 256>>>(gamma, beta);          // index 4
    int n4 = out_size / 4;                        // 15,360,000
    k_apply<<<(n4 + 255) / 256, 256>>>(out, n4);  // index 5
}

// round 13
// speedup vs baseline: 1.0611x; 1.0611x over previous
#include <cuda_runtime.h>
#include <cuda_bf16.h>

// ---------------- problem constants ----------------
#define EPS_BN 1e-5f
constexpr int Bn   = 64;          // batch
constexpr int Cin  = 64;
constexpr int Cout = 128;
constexpr int Tn   = 300;
constexpr int Vn   = 25;
constexpr int SPB  = Tn * Vn;     // 7500 sites per (b, channel)
constexpr float NTOT = 480000.0f; // B*T*V

constexpr int STILE  = 128;
constexpr int NSTILE = (SPB + STILE - 1) / STILE;  // 59
constexpr int NBLK2  = Bn * NSTILE;                // 3776

// ---------------- device workspaces (no allocs allowed) ----------------
// z is staged in d_out; k_gemm fully rewrites it on every launch before
// k_apply reads it, so graph replays stay deterministic.
__device__ __align__(16) float g_xg[Bn * Cin * SPB];    // 122.88 MB
__device__ __align__(16) float g_Wt[Cin * Cout];        // W transposed: [c][o]
__device__ float g_psum[Cout * NBLK2];                  // [o][blk]
__device__ float g_psq [Cout * NBLK2];
__device__ float g_coef[2 * Cout];                      // alpha, then bias'

// packed f32x2 FMA (SASS FFMA2) — only reachable via explicit PTX
#define FMA2(a, x, y) asm("fma.rn.f32x2 %0, %1, %2, %0;" : "+l"(a) : "l"(x), "l"(y))

union UF2 { unsigned long long u; float2 f; };

// ---------------- K1: xg = x @ adj, one 25-float row per thread -----------------
__global__ void k_xg(const float* __restrict__ x, const float* __restrict__ adj) {
    __shared__ float sx[256 * 25];    // 25.6 KB
    __shared__ float sadj[625];
    const int tid = threadIdx.x;
    const long long base = (long long)blockIdx.x * (256 * 25);

    #pragma unroll 4
    for (int i = tid; i < 256 * 25; i += 256) sx[i] = x[base + i];
    for (int i = tid; i < 625; i += 256) sadj[i] = adj[i];
    __syncthreads();

    float xr[25];
    #pragma unroll
    for (int v = 0; v < 25; v++) xr[v] = sx[tid * 25 + v];

    #pragma unroll 5
    for (int w = 0; w < 25; w++) {
        float a0 = 0.f;
        #pragma unroll
        for (int v = 0; v < 25; v++)
            a0 = fmaf(xr[v], sadj[v * 25 + w], a0);   // adj read is warp-broadcast
        sx[tid * 25 + w] = a0;
    }
    __syncthreads();

    #pragma unroll 4
    for (int i = tid; i < 256 * 25; i += 256) g_xg[base + i] = sx[i];
}

// ---------------- K1b: transpose W (Cout,Cin) -> [c][o] -------------------------
// Idempotent (pure function of W). Launched twice: the second launch is a
// deliberate pad so ncu's fixed profile window (-s 5 -c 1, empirically
// sequence index 3) lands on k_gemm instead of k_stats.
__global__ void k_wt(const float* __restrict__ W) {
    int i = blockIdx.x * 256 + threadIdx.x;      // 8192 items
    if (i < Cout * Cin) {
        int o = i >> 6, c = i & 63;              // W row-major (o, c)
        g_Wt[c * Cout + o] = W[i];
    }
}

// ---------------- K2: z[b,o,s] = sum_c W[o,c]*xg[b,c,s] + BN partials -----------
// o-pairs packed from W (contiguous in [c][o] layout); x duplicated in regs.
// Software-pipelined: next k-step's LDS issued before current step's FMAs.
__global__ void __launch_bounds__(256, 2) k_gemm(float* __restrict__ zout) {
    extern __shared__ float sm[];
    float* sW = sm;                // 64 * 128 floats (32 KB), [k][o]
    float* sX = sm + 8192;         // 64 * 128 floats (32 KB), [k][s]

    const int tid = threadIdx.x;
    const int tx = tid & 15, ty = tid >> 4;      // 16 x 16 thread grid
    const int b  = blockIdx.y;
    const int s0 = blockIdx.x * STILE;
    int valid = SPB - s0; if (valid > STILE) valid = STILE;

    #pragma unroll 4
    for (int i = tid; i < 8192; i += 256) sW[i] = g_Wt[i];   // already [c][o]
    #pragma unroll 4
    for (int i = tid; i < 8192; i += 256) {
        int c = i >> 7, s = i & 127;
        sX[i] = (s < valid) ? g_xg[((long long)(b * Cin + c)) * SPB + s0 + s] : 0.f;
    }
    __syncthreads();

    // acc[p][j]: p = o-pair (o0+2p, o0+2p+1), j = site index (tx*8 + j)
    unsigned long long acc[4][8];
    #pragma unroll
    for (int p = 0; p < 4; p++)
        #pragma unroll
        for (int j = 0; j < 8; j++) acc[p][j] = 0ULL;

    const float* wp = sW + ty * 8;     // 8 o values = 4 natural pairs
    const float* xp = sX + tx * 8;     // 8 sites

    // -------- software-pipelined mainloop (prefetch depth 1) --------
    ulonglong2 wa = *(const ulonglong2*)(wp);
    ulonglong2 wb = *(const ulonglong2*)(wp + 4);
    float4 xa = *(const float4*)(xp);
    float4 xb = *(const float4*)(xp + 4);
    wp += 128; xp += 128;

    #pragma unroll 2
    for (int k = 0; k < 63; k++) {
        // issue next k-step's loads first (LDS latency hidden behind FMAs)
        ulonglong2 wa2 = *(const ulonglong2*)(wp);
        ulonglong2 wb2 = *(const ulonglong2*)(wp + 4);
        float4 xa2 = *(const float4*)(xp);
        float4 xb2 = *(const float4*)(xp + 4);
        wp += 128; xp += 128;

        // batch all dup-packs ahead of the FMA block (decouple ALU->FMA latency)
        UF2 d[8];
        d[0].f.x = xa.x; d[0].f.y = xa.x;
        d[1].f.x = xa.y; d[1].f.y = xa.y;
        d[2].f.x = xa.z; d[2].f.y = xa.z;
        d[3].f.x = xa.w; d[3].f.y = xa.w;
        d[4].f.x = xb.x; d[4].f.y = xb.x;
        d[5].f.x = xb.y; d[5].f.y = xb.y;
        d[6].f.x = xb.z; d[6].f.y = xb.z;
        d[7].f.x = xb.w; d[7].f.y = xb.w;
        #pragma unroll
        for (int j = 0; j < 8; j++) {
            FMA2(acc[0][j], wa.x, d[j].u);
            FMA2(acc[1][j], wa.y, d[j].u);
            FMA2(acc[2][j], wb.x, d[j].u);
            FMA2(acc[3][j], wb.y, d[j].u);
        }
        wa = wa2; wb = wb2; xa = xa2; xb = xb2;   // rotate (renamed by unroll)
    }
    {   // final k-step (k = 63)
        UF2 d[8];
        d[0].f.x = xa.x; d[0].f.y = xa.x;
        d[1].f.x = xa.y; d[1].f.y = xa.y;
        d[2].f.x = xa.z; d[2].f.y = xa.z;
        d[3].f.x = xa.w; d[3].f.y = xa.w;
        d[4].f.x = xb.x; d[4].f.y = xb.x;
        d[5].f.x = xb.y; d[5].f.y = xb.y;
        d[6].f.x = xb.z; d[6].f.y = xb.z;
        d[7].f.x = xb.w; d[7].f.y = xb.w;
        #pragma unroll
        for (int j = 0; j < 8; j++) {
            FMA2(acc[0][j], wa.x, d[j].u);
            FMA2(acc[1][j], wa.y, d[j].u);
            FMA2(acc[2][j], wb.x, d[j].u);
            FMA2(acc[3][j], wb.y, d[j].u);
        }
    }

    // ---- epilogue: write z + deterministic per-o partial sums ----
    const int o0 = ty * 8;
    const int blk = blockIdx.y * NSTILE + blockIdx.x;
    const long long zbase = ((long long)b * Cout) * SPB + s0 + tx * 8;

    #pragma unroll
    for (int i = 0; i < 8; i++) {
        const int p = i >> 1, h = i & 1;
        float vals[8];
        #pragma unroll
        for (int j = 0; j < 8; j++) {
            UF2 cv; cv.u = acc[p][j];
            vals[j] = h ? cv.f.y : cv.f.x;
        }
        float s = 0.f, q = 0.f;
        #pragma unroll
        for (int j = 0; j < 8; j++) { s += vals[j]; q = fmaf(vals[j], vals[j], q); }
        // zero-padded tail sites contribute exact zeros to s and q.
        #pragma unroll
        for (int d2 = 8; d2 > 0; d2 >>= 1) {     // deterministic width-16 tree
            s += __shfl_down_sync(0xffffffffu, s, d2, 16);
            q += __shfl_down_sync(0xffffffffu, q, d2, 16);
        }
        if (tx == 0) {
            g_psum[(o0 + i) * NBLK2 + blk] = s;
            g_psq [(o0 + i) * NBLK2 + blk] = q;
        }
        long long zp = zbase + (long long)(o0 + i) * SPB;
        if (tx * 8 + 8 <= valid) {
            float4* ptr = (float4*)(zout + zp);
            ptr[0] = make_float4(vals[0], vals[1], vals[2], vals[3]);
            ptr[1] = make_float4(vals[4], vals[5], vals[6], vals[7]);
        } else {
            #pragma unroll
            for (int j = 0; j < 8; j++)
                if (tx * 8 + j < valid) zout[zp + j] = vals[j];
        }
    }
}

// ---------------- K3: reduce partials -> per-channel affine coefficients --------
__global__ void k_stats(const float* __restrict__ gamma, const float* __restrict__ beta) {
    const int o   = blockIdx.x;      // 0..127
    const int tid = threadIdx.x;     // 256 threads
    const float* ps = g_psum + o * NBLK2;
    const float* pq = g_psq  + o * NBLK2;

    float s = 0.f, q = 0.f;
    for (int bk = tid; bk < NBLK2; bk += 256) {  // coalesced
        s += ps[bk];
        q += pq[bk];
    }
    __shared__ float ss[256], sq[256];
    ss[tid] = s; sq[tid] = q;
    __syncthreads();
    #pragma unroll
    for (int d = 128; d > 0; d >>= 1) {
        if (tid < d) { ss[tid] += ss[tid + d]; sq[tid] += sq[tid + d]; }
        __syncthreads();
    }
    if (tid == 0) {
        float mean  = ss[0] / NTOT;
        float var   = sq[0] / NTOT - mean * mean;  // biased var; conv bias cancels
        float alpha = gamma[o] * rsqrtf(var + EPS_BN);
        g_coef[o]        = alpha;
        g_coef[Cout + o] = beta[o] - alpha * mean;
    }
}

// ---------------- K4: out = relu(alpha*z + bias')  in-place on d_out ------------
__global__ void k_apply(float* __restrict__ out, int n4) {
    int i = blockIdx.x * blockDim.x + threadIdx.x;
    if (i >= n4) return;
    int o = (i / (SPB / 4)) & (Cout - 1);        // (b*128+o) mod 128
    float al = g_coef[o], bb = g_coef[Cout + o];
    const float4 z = ((const float4*)out)[i];
    float4 r;
    r.x = fmaxf(fmaf(al, z.x, bb), 0.f);
    r.y = fmaxf(fmaf(al, z.y, bb), 0.f);
    r.z = fmaxf(fmaf(al, z.z, bb), 0.f);
    r.w = fmaxf(fmaf(al, z.w, bb), 0.f);
    ((float4*)out)[i] = r;
}

// ---------------- launch ----------------
extern "C" void kernel_launch(void* const* d_in, const int* in_sizes, int n_in,
                              void* d_out, int out_size) {
    const float* x     = (const float*)d_in[0];   // (64,64,300,25)
    const float* adj   = (const float*)d_in[1];   // (25,25)
    const float* W     = (const float*)d_in[2];   // (128,64)
    // d_in[3] = conv bias — cancels exactly under BatchNorm, unused
    const float* gamma = (const float*)d_in[4];   // (128,)
    const float* beta  = (const float*)d_in[5];   // (128,)
    float* out = (float*)d_out;

    const int SMEM2 = (8192 + 8192) * (int)sizeof(float);       // 64 KB
    cudaFuncSetAttribute(k_gemm, cudaFuncAttributeMaxDynamicSharedMemorySize, SMEM2);

    k_xg<<<4800, 256>>>(x, adj);                  // launch index 0
    k_wt<<<32, 256>>>(W);                         // index 1
    k_wt<<<32, 256>>>(W);                         // index 2 — pad: profiler hits index 3
    k_gemm<<<dim3(NSTILE, Bn), 256, SMEM2>>>(out);// index 3  <-- ncu target
    k_stats<<<Cout, 256>>>(gamma, beta);          // index 4
    int n4 = out_size / 4;                        // 15,360,000
    k_apply<<<(n4 + 255) / 256, 256>>>(out, n4);  // index 5
}